// round 1
// baseline (speedup 1.0000x reference)
#include <cuda_runtime.h>
#include <math.h>

// Problem constants
#define T 2048      // tokens (B*S)
#define D 1024      // model dim
#define H 2816      // ffn hidden
#define E 8         // experts
#define NPAIR (T*2) // token-expert pairs (top-2)

// GEMM tiling
#define BM 64
#define BN 64
#define BK 16
#define PAD 4

// ---- scratch (device globals; no allocation allowed) ----
__device__ int   g_pidx[NPAIR];      // expert id per pair (pair p = 2*t + k)
__device__ float g_pw[NPAIR];        // normalized combine weight per pair
__device__ int   g_count[E];         // tokens per expert
__device__ int   g_plist[E][T];      // pair ids per expert (ordered by pair id)
__device__ float g_wlist[E][T];      // weights aligned with g_plist
__device__ float g_h[(size_t)NPAIR * H];   // 46 MB: SwiGLU activations per pair
__device__ float g_yp[(size_t)NPAIR * D];  // 16.8 MB: weighted partial outputs per pair

// ---------------------------------------------------------------------------
// Gate: logits = x @ Wg^T, softmax, top-2, normalized weights.
// One block per token; 8 warps, one per expert.
// ---------------------------------------------------------------------------
__global__ void gate_kernel(const float* __restrict__ x, const float* __restrict__ Wg) {
    int t = blockIdx.x;
    int warp = threadIdx.x >> 5, lane = threadIdx.x & 31;
    __shared__ float logits[E];
    const float* xr = x + (size_t)t * D;
    const float* wr = Wg + (size_t)warp * D;
    float s = 0.f;
    #pragma unroll
    for (int j = 0; j < D / 128; j++) {
        int i = lane * 4 + j * 128;
        float4 xv = *(const float4*)(xr + i);
        float4 wv = *(const float4*)(wr + i);
        s += xv.x * wv.x + xv.y * wv.y + xv.z * wv.z + xv.w * wv.w;
    }
    #pragma unroll
    for (int o = 16; o; o >>= 1) s += __shfl_xor_sync(0xffffffffu, s, o);
    if (lane == 0) logits[warp] = s;
    __syncthreads();
    if (threadIdx.x == 0) {
        float m = logits[0];
        #pragma unroll
        for (int e2 = 1; e2 < E; e2++) m = fmaxf(m, logits[e2]);
        float p[E];
        #pragma unroll
        for (int e2 = 0; e2 < E; e2++) p[e2] = expf(logits[e2] - m);
        // top-2 (ties -> lower index, matching lax.top_k)
        int i0 = 0;
        #pragma unroll
        for (int e2 = 1; e2 < E; e2++) if (p[e2] > p[i0]) i0 = e2;
        int i1 = (i0 == 0) ? 1 : 0;
        #pragma unroll
        for (int e2 = 0; e2 < E; e2++) if (e2 != i0 && p[e2] > p[i1]) i1 = e2;
        // normalized top-k weights: softmax denom cancels
        float inv = 1.f / (p[i0] + p[i1]);
        g_pidx[2 * t]     = i0;  g_pw[2 * t]     = p[i0] * inv;
        g_pidx[2 * t + 1] = i1;  g_pw[2 * t + 1] = p[i1] * inv;
    }
}

// ---------------------------------------------------------------------------
// Deterministic per-expert list build (no atomics): one block per expert,
// ordered ballot prefix-scan over pair ids.
// ---------------------------------------------------------------------------
__global__ void build_lists_kernel() {
    int e = blockIdx.x;
    int tid = threadIdx.x;
    int lane = tid & 31, warp = tid >> 5;
    __shared__ int warp_cnt[8];
    __shared__ int base_s;
    if (tid == 0) base_s = 0;
    __syncthreads();
    for (int c = 0; c < NPAIR; c += 256) {
        int i = c + tid;
        bool m = (g_pidx[i] == e);
        unsigned bal = __ballot_sync(0xffffffffu, m);
        if (lane == 0) warp_cnt[warp] = __popc(bal);
        __syncthreads();
        int pos = base_s;
        for (int w = 0; w < warp; w++) pos += warp_cnt[w];
        pos += __popc(bal & ((1u << lane) - 1u));
        if (m) { g_plist[e][pos] = i; g_wlist[e][pos] = g_pw[i]; }
        __syncthreads();
        if (tid == 0) {
            int tot = 0;
            #pragma unroll
            for (int w = 0; w < 8; w++) tot += warp_cnt[w];
            base_s += tot;
        }
        __syncthreads();
    }
    if (tid == 0) g_count[e] = base_s;
}

// ---------------------------------------------------------------------------
// Up GEMM: h[p, n] = silu(x_t . W1[e,n,:]) * (x_t . W3[e,n,:])
// 64x64 tile, BK=16, 256 threads, 4x4 micro-tile, dual accumulators.
// ---------------------------------------------------------------------------
__global__ __launch_bounds__(256) void ffn_up_kernel(const float* __restrict__ x,
                                                     const float* __restrict__ W1,
                                                     const float* __restrict__ W3) {
    int e = blockIdx.z;
    int cnt = g_count[e];
    int m0 = blockIdx.x * BM;
    if (m0 >= cnt) return;
    int n0 = blockIdx.y * BN;

    __shared__ float xs[BK][BM + PAD];
    __shared__ float w1s[BK][BN + PAD];
    __shared__ float w3s[BK][BN + PAD];
    __shared__ int ps[BM];

    int tid = threadIdx.x;
    if (tid < BM) {
        int slot = m0 + tid;
        ps[tid] = (slot < cnt) ? g_plist[e][slot] : -1;
    }
    __syncthreads();

    int tx = tid & 15;   // n group
    int ty = tid >> 4;   // m group
    float accA[4][4] = {{0.f}};
    float accB[4][4] = {{0.f}};

    int lm  = tid >> 2;        // 0..63 tile row for loading
    int lk4 = (tid & 3) * 4;   // k offset (float4)

    const float* W1e = W1 + (size_t)e * H * D;
    const float* W3e = W3 + (size_t)e * H * D;

    int prow = ps[lm];
    const float* xrow  = x   + (size_t)((prow < 0) ? 0 : (prow >> 1)) * D;
    const float* w1row = W1e + (size_t)(n0 + lm) * D;
    const float* w3row = W3e + (size_t)(n0 + lm) * D;

    for (int k0 = 0; k0 < D; k0 += BK) {
        float4 xv = *(const float4*)(xrow  + k0 + lk4);
        float4 av = *(const float4*)(w1row + k0 + lk4);
        float4 bv = *(const float4*)(w3row + k0 + lk4);
        xs[lk4 + 0][lm] = xv.x; xs[lk4 + 1][lm] = xv.y; xs[lk4 + 2][lm] = xv.z; xs[lk4 + 3][lm] = xv.w;
        w1s[lk4 + 0][lm] = av.x; w1s[lk4 + 1][lm] = av.y; w1s[lk4 + 2][lm] = av.z; w1s[lk4 + 3][lm] = av.w;
        w3s[lk4 + 0][lm] = bv.x; w3s[lk4 + 1][lm] = bv.y; w3s[lk4 + 2][lm] = bv.z; w3s[lk4 + 3][lm] = bv.w;
        __syncthreads();
        #pragma unroll
        for (int k = 0; k < BK; k++) {
            float4 a  = *(const float4*)&xs[k][ty * 4];
            float4 b1 = *(const float4*)&w1s[k][tx * 4];
            float4 b3 = *(const float4*)&w3s[k][tx * 4];
            float ar[4] = {a.x, a.y, a.z, a.w};
            float b1r[4] = {b1.x, b1.y, b1.z, b1.w};
            float b3r[4] = {b3.x, b3.y, b3.z, b3.w};
            #pragma unroll
            for (int i = 0; i < 4; i++)
                #pragma unroll
                for (int j = 0; j < 4; j++) {
                    accA[i][j] += ar[i] * b1r[j];
                    accB[i][j] += ar[i] * b3r[j];
                }
        }
        __syncthreads();
    }

    #pragma unroll
    for (int i = 0; i < 4; i++) {
        int p = ps[ty * 4 + i];
        if (p < 0) continue;
        float* hout = g_h + (size_t)p * H + n0 + tx * 4;
        #pragma unroll
        for (int j = 0; j < 4; j++) {
            float z = accA[i][j];
            float sil = z / (1.f + expf(-z));
            hout[j] = sil * accB[i][j];
        }
    }
}

// ---------------------------------------------------------------------------
// Down GEMM: yp[p, d] = w_p * (h[p,:] . W2[e,d,:])   (K = H = 2816)
// ---------------------------------------------------------------------------
__global__ __launch_bounds__(256) void ffn_down_kernel(const float* __restrict__ W2) {
    int e = blockIdx.z;
    int cnt = g_count[e];
    int m0 = blockIdx.x * BM;
    if (m0 >= cnt) return;
    int n0 = blockIdx.y * BN;

    __shared__ float hs[BK][BM + PAD];
    __shared__ float ws[BK][BN + PAD];
    __shared__ int ps[BM];
    __shared__ float pw[BM];

    int tid = threadIdx.x;
    if (tid < BM) {
        int slot = m0 + tid;
        if (slot < cnt) { ps[tid] = g_plist[e][slot]; pw[tid] = g_wlist[e][slot]; }
        else            { ps[tid] = -1;               pw[tid] = 0.f; }
    }
    __syncthreads();

    int tx = tid & 15;
    int ty = tid >> 4;
    float acc[4][4] = {{0.f}};

    int lm  = tid >> 2;
    int lk4 = (tid & 3) * 4;

    const float* W2e = W2 + (size_t)e * D * H;
    int prow = ps[lm];
    const float* hrow = g_h + (size_t)((prow < 0) ? 0 : prow) * H;
    const float* wrow = W2e + (size_t)(n0 + lm) * H;

    for (int k0 = 0; k0 < H; k0 += BK) {
        float4 hv = *(const float4*)(hrow + k0 + lk4);
        float4 wv = *(const float4*)(wrow + k0 + lk4);
        hs[lk4 + 0][lm] = hv.x; hs[lk4 + 1][lm] = hv.y; hs[lk4 + 2][lm] = hv.z; hs[lk4 + 3][lm] = hv.w;
        ws[lk4 + 0][lm] = wv.x; ws[lk4 + 1][lm] = wv.y; ws[lk4 + 2][lm] = wv.z; ws[lk4 + 3][lm] = wv.w;
        __syncthreads();
        #pragma unroll
        for (int k = 0; k < BK; k++) {
            float4 a = *(const float4*)&hs[k][ty * 4];
            float4 b = *(const float4*)&ws[k][tx * 4];
            float ar[4] = {a.x, a.y, a.z, a.w};
            float br[4] = {b.x, b.y, b.z, b.w};
            #pragma unroll
            for (int i = 0; i < 4; i++)
                #pragma unroll
                for (int j = 0; j < 4; j++)
                    acc[i][j] += ar[i] * br[j];
        }
        __syncthreads();
    }

    #pragma unroll
    for (int i = 0; i < 4; i++) {
        int p = ps[ty * 4 + i];
        if (p < 0) continue;
        float w = pw[ty * 4 + i];
        float* yout = g_yp + (size_t)p * D + n0 + tx * 4;
        #pragma unroll
        for (int j = 0; j < 4; j++)
            yout[j] = w * acc[i][j];
    }
}

// ---------------------------------------------------------------------------
// Combine: y[t, d] = yp[2t, d] + yp[2t+1, d]
// ---------------------------------------------------------------------------
__global__ void combine_kernel(float* __restrict__ y) {
    int i = blockIdx.x * 256 + threadIdx.x;
    int t = i / D, d = i - t * D;
    y[i] = g_yp[(size_t)(2 * t) * D + d] + g_yp[(size_t)(2 * t + 1) * D + d];
}

// ---------------------------------------------------------------------------
extern "C" void kernel_launch(void* const* d_in, const int* in_sizes, int n_in,
                              void* d_out, int out_size) {
    const float* x  = (const float*)d_in[0];
    const float* Wg = (const float*)d_in[1];
    const float* W1 = (const float*)d_in[2];
    const float* W2 = (const float*)d_in[3];
    const float* W3 = (const float*)d_in[4];
    float* y = (float*)d_out;

    gate_kernel<<<T, 256>>>(x, Wg);
    build_lists_kernel<<<E, 256>>>();

    dim3 g1(T / BM, H / BN, E);   // 32 x 44 x 8 (padded; early-exit on count)
    ffn_up_kernel<<<g1, 256>>>(x, W1, W3);

    dim3 g2(T / BM, D / BN, E);   // 32 x 16 x 8
    ffn_down_kernel<<<g2, 256>>>(W2);

    combine_kernel<<<(T * D) / 256, 256>>>(y);
}

// round 3
// speedup vs baseline: 2.3620x; 2.3620x over previous
#include <cuda_runtime.h>
#include <cuda_bf16.h>
#include <cstdint>
#include <math.h>

#define T 2048      // tokens
#define D 1024      // model dim
#define H 2816      // ffn hidden
#define E 8         // experts
#define NPAIR (T*2) // token-expert pairs

#define BM 128
#define BN 64
#define BK 64
#define STRIDE 144  // padded bytes per k-row: 64*2 + 16 (bank-conflict-free)

// ---------------- device globals (no allocation allowed) ----------------
__device__ int   g_pidx[NPAIR];
__device__ float g_pw[NPAIR];
__device__ int   g_count[E];
__device__ int   g_plist[E][T];
__device__ float g_wlist[E][T];

__device__ __align__(16) __nv_bfloat16 g_xh[T*D],  g_xl[T*D];
__device__ __align__(16) __nv_bfloat16 g_W1h[(size_t)E*H*D], g_W1l[(size_t)E*H*D];
__device__ __align__(16) __nv_bfloat16 g_W3h[(size_t)E*H*D], g_W3l[(size_t)E*H*D];
__device__ __align__(16) __nv_bfloat16 g_W2h[(size_t)E*D*H], g_W2l[(size_t)E*D*H];
__device__ __align__(16) __nv_bfloat16 g_hh[(size_t)NPAIR*H], g_hl[(size_t)NPAIR*H];
__device__ float g_yp[(size_t)NPAIR*D];

// ---------------- helpers ----------------
__device__ __forceinline__ uint32_t smem_u32(const void* p) {
    uint32_t a;
    asm("{ .reg .u64 t; cvta.to.shared.u64 t, %1; cvt.u32.u64 %0, t; }" : "=r"(a) : "l"(p));
    return a;
}
__device__ __forceinline__ void cp16(uint32_t dst, const void* src) {
    asm volatile("cp.async.cg.shared.global [%0], [%1], 16;" :: "r"(dst), "l"(src));
}
#define CP_COMMIT() asm volatile("cp.async.commit_group;" ::: "memory")
#define CP_WAIT1()  asm volatile("cp.async.wait_group 1;" ::: "memory")

__device__ __forceinline__ void mma16816(float* c, const uint32_t* a, const uint32_t* b) {
    asm volatile("mma.sync.aligned.m16n8k16.row.col.f32.bf16.bf16.f32 "
        "{%0,%1,%2,%3}, {%4,%5,%6,%7}, {%8,%9}, {%0,%1,%2,%3};"
        : "+f"(c[0]), "+f"(c[1]), "+f"(c[2]), "+f"(c[3])
        : "r"(a[0]), "r"(a[1]), "r"(a[2]), "r"(a[3]), "r"(b[0]), "r"(b[1]));
}
// A fragment (m16 x k16), rows = rm.., direct LDS.32 (conflict-free w/ STRIDE=144)
__device__ __forceinline__ void ldA(uint32_t* a, const char* tile, int rm, int kk, int g, int q) {
    const char* p = tile + (rm + g) * STRIDE + (kk + q * 2) * 2;
    a[0] = *(const uint32_t*)p;
    a[1] = *(const uint32_t*)(p + 8 * STRIDE);
    a[2] = *(const uint32_t*)(p + 16);
    a[3] = *(const uint32_t*)(p + 8 * STRIDE + 16);
}
// B fragment (k16 x n8), rows of tile = n
__device__ __forceinline__ void ldB(uint32_t* b, const char* tile, int cn, int kk, int g, int q) {
    const char* p = tile + (cn + g) * STRIDE + (kk + q * 2) * 2;
    b[0] = *(const uint32_t*)p;
    b[1] = *(const uint32_t*)(p + 16);
}
__device__ __forceinline__ uint32_t b2u(__nv_bfloat162 v) { return *reinterpret_cast<uint32_t*>(&v); }

// ---------------- split fp32 -> bf16 hi/lo ----------------
__global__ void split_kernel(const float* __restrict__ src, __nv_bfloat16* __restrict__ hi,
                             __nv_bfloat16* __restrict__ lo, int n4) {
    int i = blockIdx.x * 256 + threadIdx.x;
    if (i >= n4) return;
    float4 v = ((const float4*)src)[i];
    __nv_bfloat162 h0 = __floats2bfloat162_rn(v.x, v.y);
    __nv_bfloat162 h1 = __floats2bfloat162_rn(v.z, v.w);
    __nv_bfloat162 l0 = __floats2bfloat162_rn(v.x - __bfloat162float(h0.x), v.y - __bfloat162float(h0.y));
    __nv_bfloat162 l1 = __floats2bfloat162_rn(v.z - __bfloat162float(h1.x), v.w - __bfloat162float(h1.y));
    ((uint2*)hi)[i] = make_uint2(b2u(h0), b2u(h1));
    ((uint2*)lo)[i] = make_uint2(b2u(l0), b2u(l1));
}

// ---------------- gate / routing (unchanged from passing R1) ----------------
__global__ void gate_kernel(const float* __restrict__ x, const float* __restrict__ Wg) {
    int t = blockIdx.x;
    int warp = threadIdx.x >> 5, lane = threadIdx.x & 31;
    __shared__ float logits[E];
    const float* xr = x + (size_t)t * D;
    const float* wr = Wg + (size_t)warp * D;
    float s = 0.f;
    #pragma unroll
    for (int j = 0; j < D / 128; j++) {
        int i = lane * 4 + j * 128;
        float4 xv = *(const float4*)(xr + i);
        float4 wv = *(const float4*)(wr + i);
        s += xv.x * wv.x + xv.y * wv.y + xv.z * wv.z + xv.w * wv.w;
    }
    #pragma unroll
    for (int o = 16; o; o >>= 1) s += __shfl_xor_sync(0xffffffffu, s, o);
    if (lane == 0) logits[warp] = s;
    __syncthreads();
    if (threadIdx.x == 0) {
        float m = logits[0];
        #pragma unroll
        for (int e2 = 1; e2 < E; e2++) m = fmaxf(m, logits[e2]);
        float p[E];
        #pragma unroll
        for (int e2 = 0; e2 < E; e2++) p[e2] = expf(logits[e2] - m);
        int i0 = 0;
        #pragma unroll
        for (int e2 = 1; e2 < E; e2++) if (p[e2] > p[i0]) i0 = e2;
        int i1 = (i0 == 0) ? 1 : 0;
        #pragma unroll
        for (int e2 = 0; e2 < E; e2++) if (e2 != i0 && p[e2] > p[i1]) i1 = e2;
        float inv = 1.f / (p[i0] + p[i1]);
        g_pidx[2*t]   = i0; g_pw[2*t]   = p[i0] * inv;
        g_pidx[2*t+1] = i1; g_pw[2*t+1] = p[i1] * inv;
    }
}

__global__ void build_lists_kernel() {
    int e = blockIdx.x, tid = threadIdx.x;
    int lane = tid & 31, warp = tid >> 5;
    __shared__ int warp_cnt[8];
    __shared__ int base_s;
    if (tid == 0) base_s = 0;
    __syncthreads();
    for (int c = 0; c < NPAIR; c += 256) {
        int i = c + tid;
        bool m = (g_pidx[i] == e);
        unsigned bal = __ballot_sync(0xffffffffu, m);
        if (lane == 0) warp_cnt[warp] = __popc(bal);
        __syncthreads();
        int pos = base_s;
        for (int w = 0; w < warp; w++) pos += warp_cnt[w];
        pos += __popc(bal & ((1u << lane) - 1u));
        if (m) { g_plist[e][pos] = i; g_wlist[e][pos] = g_pw[i]; }
        __syncthreads();
        if (tid == 0) {
            int tot = 0;
            #pragma unroll
            for (int w = 0; w < 8; w++) tot += warp_cnt[w];
            base_s += tot;
        }
        __syncthreads();
    }
    if (tid == 0) g_count[e] = base_s;
}

// ---------------- UP GEMM: h = silu(x W1^T) * (x W3^T), split-bf16 mma ----------------
// Stage layout (bytes): Ah 0, Al 18432, B1h 36864, B1l 46080, B3h 55296, B3l 64512
#define UP_STG 73728
#define UP_SMEM (1024 + 2*UP_STG)

__global__ __launch_bounds__(256, 1) void ffn_up_mma() {
    int e = blockIdx.z;
    int cnt = g_count[e];
    int m0 = blockIdx.x * BM;
    if (m0 >= cnt) return;
    int n0 = blockIdx.y * BN;

    extern __shared__ __align__(128) char smem[];
    int* ps = (int*)smem;
    int tid = threadIdx.x;
    if (tid < BM) { int s = m0 + tid; ps[tid] = (s < cnt) ? g_plist[e][s] : -1; }
    __syncthreads();

    char* tiles = smem + 1024;
    uint32_t tiles_u = smem_u32(tiles);
    const size_t wbase = (size_t)e * H * D + (size_t)n0 * D;
    const int NS = D / BK;  // 16

    auto issue = [&](int s) {
        uint32_t tb = tiles_u + (s & 1) * UP_STG;
        int k0 = s * BK;
        #pragma unroll
        for (int j = 0; j < 16; j++) {
            int idx = tid + j * 256;
            if (idx < 2048) {  // A: x rows gathered by pair
                int part = idx >> 10, rem = idx & 1023, r = rem >> 3, c = rem & 7;
                int pr = ps[r];
                int tok = (pr < 0) ? 0 : (pr >> 1);
                const __nv_bfloat16* src = (part ? g_xl : g_xh) + (size_t)tok * D + k0 + c * 8;
                cp16(tb + part * 18432 + r * STRIDE + c * 16, src);
            } else {           // B: W1 / W3 rows
                int idx2 = idx - 2048;
                int mat = idx2 >> 10, rem = idx2 & 1023, part = rem >> 9, r = (rem >> 3) & 63, c = rem & 7;
                const __nv_bfloat16* base = mat ? (part ? g_W3l : g_W3h) : (part ? g_W1l : g_W1h);
                cp16(tb + 36864 + mat * 18432 + part * 9216 + r * STRIDE + c * 16,
                     base + wbase + (size_t)r * D + k0 + c * 8);
            }
        }
    };

    int wid = tid >> 5, lane = tid & 31;
    int wm = wid & 3, wn = wid >> 2;
    int g = lane >> 2, q = lane & 3;

    float a1[2][4][4], a3[2][4][4];
    #pragma unroll
    for (int i = 0; i < 2; i++)
        #pragma unroll
        for (int j = 0; j < 4; j++)
            #pragma unroll
            for (int k = 0; k < 4; k++) { a1[i][j][k] = 0.f; a3[i][j][k] = 0.f; }

    issue(0); CP_COMMIT();
    issue(1); CP_COMMIT();

    for (int s = 0; s < NS; s++) {
        CP_WAIT1();
        __syncthreads();
        const char* tb = tiles + (s & 1) * UP_STG;
        const char* Ah = tb,           *Al  = tb + 18432;
        const char* B1h = tb + 36864,  *B1l = tb + 46080;
        const char* B3h = tb + 55296,  *B3l = tb + 64512;
        #pragma unroll
        for (int kk = 0; kk < BK; kk += 16) {
            uint32_t fAh[2][4], fAl[2][4];
            #pragma unroll
            for (int mi = 0; mi < 2; mi++) {
                ldA(fAh[mi], Ah, wm * 32 + mi * 16, kk, g, q);
                ldA(fAl[mi], Al, wm * 32 + mi * 16, kk, g, q);
            }
            {   // W1
                uint32_t bh[4][2], bl[4][2];
                #pragma unroll
                for (int nj = 0; nj < 4; nj++) {
                    ldB(bh[nj], B1h, wn * 32 + nj * 8, kk, g, q);
                    ldB(bl[nj], B1l, wn * 32 + nj * 8, kk, g, q);
                }
                #pragma unroll
                for (int mi = 0; mi < 2; mi++)
                    #pragma unroll
                    for (int nj = 0; nj < 4; nj++) {
                        mma16816(a1[mi][nj], fAh[mi], bh[nj]);
                        mma16816(a1[mi][nj], fAh[mi], bl[nj]);
                        mma16816(a1[mi][nj], fAl[mi], bh[nj]);
                    }
            }
            {   // W3
                uint32_t bh[4][2], bl[4][2];
                #pragma unroll
                for (int nj = 0; nj < 4; nj++) {
                    ldB(bh[nj], B3h, wn * 32 + nj * 8, kk, g, q);
                    ldB(bl[nj], B3l, wn * 32 + nj * 8, kk, g, q);
                }
                #pragma unroll
                for (int mi = 0; mi < 2; mi++)
                    #pragma unroll
                    for (int nj = 0; nj < 4; nj++) {
                        mma16816(a3[mi][nj], fAh[mi], bh[nj]);
                        mma16816(a3[mi][nj], fAh[mi], bl[nj]);
                        mma16816(a3[mi][nj], fAl[mi], bh[nj]);
                    }
            }
        }
        __syncthreads();
        if (s + 2 < NS) issue(s + 2);
        CP_COMMIT();
    }

    // epilogue: silu(z)*u, split to hi/lo, store bf16x2
    #pragma unroll
    for (int mi = 0; mi < 2; mi++) {
        #pragma unroll
        for (int nj = 0; nj < 4; nj++) {
            int lr0 = wm * 32 + mi * 16 + g, lr1 = lr0 + 8;
            int n = n0 + wn * 32 + nj * 8 + q * 2;
            float* c1 = a1[mi][nj];
            float* c3 = a3[mi][nj];
            #pragma unroll
            for (int half = 0; half < 2; half++) {
                int p = ps[half ? lr1 : lr0];
                if (p < 0) continue;
                float z0 = c1[half * 2], z1 = c1[half * 2 + 1];
                float u0 = c3[half * 2], u1 = c3[half * 2 + 1];
                float h0 = (z0 / (1.f + __expf(-z0))) * u0;
                float h1 = (z1 / (1.f + __expf(-z1))) * u1;
                __nv_bfloat162 hh = __floats2bfloat162_rn(h0, h1);
                __nv_bfloat162 ll = __floats2bfloat162_rn(h0 - __bfloat162float(hh.x),
                                                          h1 - __bfloat162float(hh.y));
                *(uint32_t*)(g_hh + (size_t)p * H + n) = b2u(hh);
                *(uint32_t*)(g_hl + (size_t)p * H + n) = b2u(ll);
            }
        }
    }
}

// ---------------- DOWN GEMM: yp = w * (h W2^T), split-bf16 mma ----------------
// Stage layout: Ah 0, Al 18432, Bh 36864, Bl 46080
#define DN_STG 55296
#define DN_SMEM (1024 + 2*DN_STG)

__global__ __launch_bounds__(256, 1) void ffn_down_mma() {
    int e = blockIdx.z;
    int cnt = g_count[e];
    int m0 = blockIdx.x * BM;
    if (m0 >= cnt) return;
    int n0 = blockIdx.y * BN;

    extern __shared__ __align__(128) char smem[];
    int* ps = (int*)smem;
    float* pwS = (float*)(smem + 512);
    int tid = threadIdx.x;
    if (tid < BM) {
        int s = m0 + tid;
        if (s < cnt) { ps[tid] = g_plist[e][s]; pwS[tid] = g_wlist[e][s]; }
        else         { ps[tid] = -1;            pwS[tid] = 0.f; }
    }
    __syncthreads();

    char* tiles = smem + 1024;
    uint32_t tiles_u = smem_u32(tiles);
    const size_t wbase = (size_t)e * D * H + (size_t)n0 * H;
    const int NS = H / BK;  // 44

    auto issue = [&](int s) {
        uint32_t tb = tiles_u + (s & 1) * DN_STG;
        int k0 = s * BK;
        #pragma unroll
        for (int j = 0; j < 12; j++) {
            int idx = tid + j * 256;
            if (idx < 2048) {  // A: h rows by pair
                int part = idx >> 10, rem = idx & 1023, r = rem >> 3, c = rem & 7;
                int p = ps[r];
                int pr = (p < 0) ? 0 : p;
                const __nv_bfloat16* src = (part ? g_hl : g_hh) + (size_t)pr * H + k0 + c * 8;
                cp16(tb + part * 18432 + r * STRIDE + c * 16, src);
            } else {           // B: W2 rows
                int idx2 = idx - 2048;
                int part = idx2 >> 9, r = (idx2 >> 3) & 63, c = idx2 & 7;
                const __nv_bfloat16* base = part ? g_W2l : g_W2h;
                cp16(tb + 36864 + part * 9216 + r * STRIDE + c * 16,
                     base + wbase + (size_t)r * H + k0 + c * 8);
            }
        }
    };

    int wid = tid >> 5, lane = tid & 31;
    int wm = wid & 3, wn = wid >> 2;
    int g = lane >> 2, q = lane & 3;

    float acc[2][4][4];
    #pragma unroll
    for (int i = 0; i < 2; i++)
        #pragma unroll
        for (int j = 0; j < 4; j++)
            #pragma unroll
            for (int k = 0; k < 4; k++) acc[i][j][k] = 0.f;

    issue(0); CP_COMMIT();
    issue(1); CP_COMMIT();

    for (int s = 0; s < NS; s++) {
        CP_WAIT1();
        __syncthreads();
        const char* tb = tiles + (s & 1) * DN_STG;
        const char* Ah = tb,          *Al = tb + 18432;
        const char* Bh = tb + 36864,  *Bl = tb + 46080;
        #pragma unroll
        for (int kk = 0; kk < BK; kk += 16) {
            uint32_t fAh[2][4], fAl[2][4];
            #pragma unroll
            for (int mi = 0; mi < 2; mi++) {
                ldA(fAh[mi], Ah, wm * 32 + mi * 16, kk, g, q);
                ldA(fAl[mi], Al, wm * 32 + mi * 16, kk, g, q);
            }
            uint32_t bh[4][2], bl[4][2];
            #pragma unroll
            for (int nj = 0; nj < 4; nj++) {
                ldB(bh[nj], Bh, wn * 32 + nj * 8, kk, g, q);
                ldB(bl[nj], Bl, wn * 32 + nj * 8, kk, g, q);
            }
            #pragma unroll
            for (int mi = 0; mi < 2; mi++)
                #pragma unroll
                for (int nj = 0; nj < 4; nj++) {
                    mma16816(acc[mi][nj], fAh[mi], bh[nj]);
                    mma16816(acc[mi][nj], fAh[mi], bl[nj]);
                    mma16816(acc[mi][nj], fAl[mi], bh[nj]);
                }
        }
        __syncthreads();
        if (s + 2 < NS) issue(s + 2);
        CP_COMMIT();
    }

    #pragma unroll
    for (int mi = 0; mi < 2; mi++) {
        #pragma unroll
        for (int nj = 0; nj < 4; nj++) {
            int lr0 = wm * 32 + mi * 16 + g, lr1 = lr0 + 8;
            int n = n0 + wn * 32 + nj * 8 + q * 2;
            float* c = acc[mi][nj];
            #pragma unroll
            for (int half = 0; half < 2; half++) {
                int lr = half ? lr1 : lr0;
                int p = ps[lr];
                if (p < 0) continue;
                float w = pwS[lr];
                float2 v = make_float2(w * c[half * 2], w * c[half * 2 + 1]);
                *(float2*)(g_yp + (size_t)p * D + n) = v;
            }
        }
    }
}

// ---------------- combine ----------------
__global__ void combine_kernel(float* __restrict__ y) {
    int i = blockIdx.x * 256 + threadIdx.x;
    int t = i / D, d = i - t * D;
    y[i] = g_yp[(size_t)(2 * t) * D + d] + g_yp[(size_t)(2 * t + 1) * D + d];
}

// ---------------- launch ----------------
extern "C" void kernel_launch(void* const* d_in, const int* in_sizes, int n_in,
                              void* d_out, int out_size) {
    const float* x  = (const float*)d_in[0];
    const float* Wg = (const float*)d_in[1];
    const float* W1 = (const float*)d_in[2];
    const float* W2 = (const float*)d_in[3];
    const float* W3 = (const float*)d_in[4];
    float* y = (float*)d_out;

    static int attr_done = 0;
    if (!attr_done) {
        cudaFuncSetAttribute(ffn_up_mma,   cudaFuncAttributeMaxDynamicSharedMemorySize, UP_SMEM);
        cudaFuncSetAttribute(ffn_down_mma, cudaFuncAttributeMaxDynamicSharedMemorySize, DN_SMEM);
        attr_done = 1;
    }

    // pre-split fp32 -> bf16 hi/lo
    {
        int nW = (int)((size_t)E * H * D / 4);       // 5,767,168 float4s
        int nX = T * D / 4;
        __nv_bfloat16 *w1h, *w1l, *w3h, *w3l, *w2h, *w2l, *xh, *xl;
        cudaGetSymbolAddress((void**)&w1h, g_W1h); cudaGetSymbolAddress((void**)&w1l, g_W1l);
        cudaGetSymbolAddress((void**)&w3h, g_W3h); cudaGetSymbolAddress((void**)&w3l, g_W3l);
        cudaGetSymbolAddress((void**)&w2h, g_W2h); cudaGetSymbolAddress((void**)&w2l, g_W2l);
        cudaGetSymbolAddress((void**)&xh,  g_xh);  cudaGetSymbolAddress((void**)&xl,  g_xl);
        split_kernel<<<(nW + 255) / 256, 256>>>(W1, w1h, w1l, nW);
        split_kernel<<<(nW + 255) / 256, 256>>>(W3, w3h, w3l, nW);
        split_kernel<<<(nW + 255) / 256, 256>>>(W2, w2h, w2l, nW);
        split_kernel<<<(nX + 255) / 256, 256>>>(x,  xh,  xl,  nX);
    }

    gate_kernel<<<T, 256>>>(x, Wg);
    build_lists_kernel<<<E, 256>>>();

    dim3 g1(T / BM, H / BN, E);   // 16 x 44 x 8
    ffn_up_mma<<<g1, 256, UP_SMEM>>>();

    dim3 g2(T / BM, D / BN, E);   // 16 x 16 x 8
    ffn_down_mma<<<g2, 256, DN_SMEM>>>();

    combine_kernel<<<(T * D) / 256, 256>>>(y);
}